// round 11
// baseline (speedup 1.0000x reference)
#include <cuda_runtime.h>

// out[b,s,d] = x[b,s,d] + enc(s,d)
//   enc(s,d) = sin(s / 10000^(d/D)) if d even else cos(s / 10000^(d/D))
// Shapes: B=8, S=4096, D=1024, fp32. 268 MB traffic (algorithmic floor).
//
// FINAL — kernel of record (43.49us end-to-end, reproduced 4x; ~5.9 TB/s =
// ~74% of 8 TB/s HBM3e spec; rel_err 1.8e-5).
//
// Session conclusion (R1-R10): the op is pinned at the mixed 1:1 R/W HBM
// ceiling. Proven non-binding: occupancy (40% == 82%), MLP (4 == 8), access
// width (LDG.128 == 256-bit v8), load policy (default == .cs), store policy
// (.cs == .wt == default), block size (256 == 512). Persistent grid-stride
// regressed 5% (broke front-batched read bursts). Per-element non-reusing
// kernel ruled out analytically (~65us of transcendental compute would bind).
// Remaining gap to spec is DRAM bus-turnaround on the interleaved R/W
// stream — not addressable from SASS.
//
// Structure: one thread owns one (s, d..d+3) float4 column; computes the 4
// sin/cos encoding values ONCE (hidden under the 8 in-flight loads) and
// applies them to all 8 batch slices (8x reuse of transcendentals). Flat
// launch, MLP=8 front-batched loads, evict-first stores.

#define B_ 8
#define S_ 4096
#define D_ 1024
#define SD4_ ((S_ * D_) / 4)   // 1,048,576 float4 tiles per batch slice
#define TPB 512

__global__ __launch_bounds__(TPB) void pe_add_kernel(
    const float4* __restrict__ x, float4* __restrict__ out)
{
    const int idx4 = blockIdx.x * TPB + threadIdx.x;          // [0, SD4_)
    const int d0   = (idx4 & (D_ / 4 - 1)) << 2;              // element column in D
    const float sf = (float)(idx4 >> 8);                      // s = idx4 / 256

    // Front-batch all 8 batch-slice loads -> 8 outstanding LDG.128 per thread.
    float4 v[B_];
#pragma unroll
    for (int b = 0; b < B_; b++)
        v[b] = x[(long long)b * SD4_ + idx4];

    // Encoding float4, computed once, hidden under the in-flight loads.
    // angle(d) = s * 10000^(-d/D) = s * exp2(-d * log2(1e4)/D)
    const float c = -(13.287712379549449f / 1024.0f);
    const float e0 = sinf(sf * exp2f((float)(d0 + 0) * c));   // even d -> sin
    const float e1 = cosf(sf * exp2f((float)(d0 + 1) * c));   // odd d  -> cos
    const float e2 = sinf(sf * exp2f((float)(d0 + 2) * c));
    const float e3 = cosf(sf * exp2f((float)(d0 + 3) * c));

#pragma unroll
    for (int b = 0; b < B_; b++) {
        float4 r = v[b];
        r.x += e0; r.y += e1; r.z += e2; r.w += e3;
        __stcs(out + (long long)b * SD4_ + idx4, r);
    }
}

extern "C" void kernel_launch(void* const* d_in, const int* in_sizes, int n_in,
                              void* d_out, int out_size)
{
    const float4* x = (const float4*)d_in[0];
    float4* out = (float4*)d_out;
    pe_add_kernel<<<SD4_ / TPB, TPB>>>(x, out);
}

// round 13
// speedup vs baseline: 1.0021x; 1.0021x over previous
#include <cuda_runtime.h>
#include <cstdint>

// out[b,s,d] = x[b,s,d] + enc(s,d); B=8,S=4096,D=1024 fp32. 268 MB traffic.
//
// R13 (= R12 with compile fix): TMA bulk-store write path. R1-R11 pinned
// every thread-side axis at the mixed 1:1 R/W HBM ceiling (~74% of spec,
// ~5.9 TB/s). Hypothesis: the fine-grained STG read/write interleave costs
// DRAM bus-turnaround; cp.async.bulk emits 4KB contiguous write
// transactions which may let the MC group same-direction bursts. Each
// 256-thr block computes 8 batch slices x 4KB, stages in SMEM, one elected
// thread issues 8 bulk stores.

#define B_ 8
#define S_ 4096
#define D_ 1024
#define SD4_ ((S_ * D_) / 4)   // 1,048,576 float4 tiles per batch slice
#define TPB 256
#define SLICE_BYTES (TPB * 16) // 4096 B contiguous per batch slice per block

__global__ __launch_bounds__(TPB) void pe_add_kernel(
    const float4* __restrict__ x, float4* __restrict__ out)
{
    __shared__ __align__(128) float4 stage[B_][TPB];   // 32 KB

    const int tid   = threadIdx.x;
    const int idx4  = blockIdx.x * TPB + tid;          // [0, SD4_)
    const int d0    = (idx4 & (D_ / 4 - 1)) << 2;
    const float sf  = (float)(idx4 >> 8);              // s = idx4 / 256

    // Front-batch all 8 batch-slice loads (MLP=8).
    float4 v[B_];
#pragma unroll
    for (int b = 0; b < B_; b++)
        v[b] = x[(long long)b * SD4_ + idx4];

    // Encoding computed once, hidden under in-flight loads.
    const float c = -(13.287712379549449f / 1024.0f); // -log2(1e4)/D
    const float e0 = sinf(sf * exp2f((float)(d0 + 0) * c));
    const float e1 = cosf(sf * exp2f((float)(d0 + 1) * c));
    const float e2 = sinf(sf * exp2f((float)(d0 + 2) * c));
    const float e3 = cosf(sf * exp2f((float)(d0 + 3) * c));

#pragma unroll
    for (int b = 0; b < B_; b++) {
        float4 r = v[b];
        r.x += e0; r.y += e1; r.z += e2; r.w += e3;
        stage[b][tid] = r;
    }

    __syncthreads();
    // Order generic SMEM writes before async-proxy (TMA) reads of SMEM.
    asm volatile("fence.proxy.async.shared::cta;" ::: "memory");

    // One elected thread issues 8 x 4KB bulk stores (1D, no tensor map).
    if (tid == 0) {
        const long long blk_off = (long long)blockIdx.x * TPB;
#pragma unroll
        for (int b = 0; b < B_; b++) {
            unsigned int saddr;
            asm("{ .reg .u64 t; cvta.to.shared.u64 t, %1; cvt.u32.u64 %0, t; }"
                : "=r"(saddr) : "l"(&stage[b][0]));
            float4* gdst = out + (long long)b * SD4_ + blk_off;
            asm volatile(
                "cp.async.bulk.global.shared::cta.bulk_group [%0], [%1], %2;"
                :: "l"(gdst), "r"(saddr), "r"((unsigned int)SLICE_BYTES)
                : "memory");
        }
        asm volatile("cp.async.bulk.commit_group;" ::: "memory");
        asm volatile("cp.async.bulk.wait_group.read 0;" ::: "memory");
    }
}

extern "C" void kernel_launch(void* const* d_in, const int* in_sizes, int n_in,
                              void* d_out, int out_size)
{
    const float4* x = (const float4*)d_in[0];
    float4* out = (float4*)d_out;
    pe_add_kernel<<<SD4_ / TPB, TPB>>>(x, out);
}